// round 16
// baseline (speedup 1.0000x reference)
#include <cuda_runtime.h>
#include <cuda_bf16.h>
#include <math.h>
#include <stdint.h>

#define BB 8
#define TT 10
#define NP 128
#define IMGS (BB*TT*NP)      // 10240
#define NT (TT-1)            // 9
#define MATSZ (NP*NP)        // 16384
#define TAUF 0.07f

// ---------------- device scratch (static, no allocations) ----------------
__device__ float g_emb[IMGS*128];          // normalized embeddings
__device__ float g_Lb[2][BB*8*MATSZ];      // prefix-product ping-pong
__device__ float g_Rb[2][BB*8*MATSZ];      // suffix-product ping-pong
__device__ float g_At[BB*8*MATSZ];
__device__ float g_partial[64];

// ===================== HMMA helpers (baseline PTX, sm_80+) =====================
__device__ __forceinline__ uint32_t smem_u32(const void* p) {
    uint32_t a;
    asm("{ .reg .u64 t; cvta.to.shared.u64 t, %1; cvt.u32.u64 %0, t; }" : "=r"(a) : "l"(p));
    return a;
}
__device__ __forceinline__ void ldm4(uint32_t* r, uint32_t addr) {
    asm volatile("ldmatrix.sync.aligned.m8n8.x4.shared.b16 {%0,%1,%2,%3}, [%4];"
        : "=r"(r[0]), "=r"(r[1]), "=r"(r[2]), "=r"(r[3]) : "r"(addr));
}
__device__ __forceinline__ void mma16816(float* d, const uint32_t* a, uint32_t b0, uint32_t b1) {
    asm volatile(
        "mma.sync.aligned.m16n8k16.row.col.f32.bf16.bf16.f32 "
        "{%0,%1,%2,%3}, {%4,%5,%6,%7}, {%8,%9}, {%0,%1,%2,%3};"
        : "+f"(d[0]), "+f"(d[1]), "+f"(d[2]), "+f"(d[3])
        : "r"(a[0]), "r"(a[1]), "r"(a[2]), "r"(a[3]), "r"(b0), "r"(b1));
}

// ===================== fused encoder (HMMA, split bf16, kt-outer pipelined) ==========
// CTA = 2 images, 8 warps. conv1 -> regs; v = h + m; conv2 GEMM [128,288,64]
// = hh + hm + mh. Warp tile 32x32. Per kt: load 8 frags once, issue 24 mma,
// double-buffered so ldmatrix of kt+1 overlaps mma of kt.
#define KS 296                         // padded K stride (bf16) -> 592B rows
#define E_AHI 0
#define E_ALO 75776                    // 128*296*2  (A_m)
#define E_BHI 151552
#define E_BLO 189440                   // + 64*296*2 (B_m)
#define E_B2  227328                   // 64 f32
#define E_POOL 227584
#define E_NRM  228608
#define ENC_SMEM_BYTES 228640
#define DA ((uint32_t)(E_ALO - E_AHI))
#define DBo ((uint32_t)(E_BLO - E_BHI))

extern "C" __global__ void __launch_bounds__(256, 1)
encoder_hmma_kernel(const float* __restrict__ seq,
    const float* __restrict__ c1w, const float* __restrict__ c1b,
    const float* __restrict__ c2w, const float* __restrict__ c2b,
    const float* __restrict__ lw,  const float* __restrict__ lb)
{
    extern __shared__ __align__(16) char esm[];
    const int tid = threadIdx.x;
    const int wid = tid >> 5, lane = tid & 31;
    const int g = blockIdx.x;

    // ---- phase 1: stage img + conv1 weights into (future) A region ----
    float* imgS = (float*)(esm + E_AHI);           // 2048 f32
    float* w1S  = (float*)(esm + E_AHI + 8192);    // 288 f32
    float* b1S  = w1S + 288;                       // 32 f32
    for (int i = tid; i < 2048; i += 256) imgS[i] = seq[(size_t)g*2048 + i];
    for (int i = tid; i < 288;  i += 256) w1S[i] = c1w[i];
    if (tid < 32)  b1S[tid] = c1b[tid];
    __syncthreads();

    // ---- conv1 into regs: ic = tid&31, positions pos = i*8 + (tid>>5) ----
    const int ic = tid & 31;
    const int wgrp = tid >> 5;
    float wr[9];
    #pragma unroll
    for (int j = 0; j < 9; j++) wr[j] = w1S[ic*9 + j];
    const float bias1 = b1S[ic];
    float v[64];
    #pragma unroll
    for (int i = 0; i < 64; i++) {
        int pos = i*8 + wgrp;                   // 0..511
        int im = pos >> 8, y = (pos >> 4) & 15, x = pos & 15;
        const float* ib = imgS + im*1024;
        float s = bias1;
        #pragma unroll
        for (int dy2 = 0; dy2 < 3; dy2++) {
            int iy = 2*y + dy2;
            if (iy < 32) {
                #pragma unroll
                for (int dx2 = 0; dx2 < 3; dx2++) {
                    int ix = 2*x + dx2;
                    if (ix < 32) s += ib[iy*32 + ix] * wr[dy2*3 + dx2];
                }
            }
        }
        v[i] = fmaxf(s, 0.f);
    }
    __syncthreads();

    // ---- phase 2: zero A region; build B_h/B_m; stage conv2 bias ----
    {
        uint4 z4 = make_uint4(0u, 0u, 0u, 0u);
        uint4* az = (uint4*)esm;                // bytes [0, 151552)
        for (int i = tid; i < 151552/16; i += 256) az[i] = z4;
    }
    {
        __nv_bfloat16* Bh = (__nv_bfloat16*)(esm + E_BHI);
        __nv_bfloat16* Bm = (__nv_bfloat16*)(esm + E_BLO);
        for (int i = tid; i < 64*288; i += 256) {
            int oc = i / 288; int k = i - oc*288;
            float w = __ldg(&c2w[i]);
            __nv_bfloat16 h = __float2bfloat16(w);
            float r1 = w - __bfloat162float(h);
            Bh[oc*KS + k] = h;
            Bm[oc*KS + k] = __float2bfloat16(r1);
        }
    }
    float* b2S = (float*)(esm + E_B2);
    if (tid < 64) b2S[tid] = c2b[tid];
    __syncthreads();

    // ---- phase 3: scatter conv1 regs into A_h / A_m ----
    {
        __nv_bfloat16* Ah = (__nv_bfloat16*)(esm + E_AHI);
        __nv_bfloat16* Am = (__nv_bfloat16*)(esm + E_ALO);
        #pragma unroll
        for (int i = 0; i < 64; i++) {
            int pos = i*8 + wgrp;
            int im = pos >> 8, y = (pos >> 4) & 15, x = pos & 15;
            float val = v[i];
            __nv_bfloat16 hv = __float2bfloat16(val);
            float r1 = val - __bfloat162float(hv);
            __nv_bfloat16 mv = __float2bfloat16(r1);
            #pragma unroll
            for (int dy = 0; dy < 3; dy++) {
                int ty = y - dy;
                if (ty >= 0 && (ty & 1) == 0) {
                    int oy = ty >> 1;
                    #pragma unroll
                    for (int dx = 0; dx < 3; dx++) {
                        int tx = x - dx;
                        if (tx >= 0 && (tx & 1) == 0) {
                            int ox = tx >> 1;
                            int r = im*64 + oy*8 + ox;
                            int k = ic*9 + dy*3 + dx;
                            Ah[r*KS + k] = hv;
                            Am[r*KS + k] = mv;
                        }
                    }
                }
            }
        }
    }
    __syncthreads();

    // ---- phase 4: HMMA, kt-outer, 8 frag loads + 24 mma per kt, double-buffered ----
    const uint32_t sb = smem_u32(esm);
    const int mrow = (wid & 3) * 32;
    const int ncol = (wid >> 2) * 32;
    float acc[2][4][4];
    #pragma unroll
    for (int a = 0; a < 2; a++)
        #pragma unroll
        for (int b = 0; b < 4; b++)
            #pragma unroll
            for (int c = 0; c < 4; c++) acc[a][b][c] = 0.f;

    const uint32_t aAddr = sb + E_AHI +
        (uint32_t)(((mrow + (lane & 15)) * KS + ((lane & 16) ? 8 : 0)) * 2);
    const uint32_t bAddr = sb + E_BHI +
        (uint32_t)(((ncol + (lane & 7) + ((lane & 16) ? 8 : 0)) * KS + ((lane & 8) ? 8 : 0)) * 2);

    // fragment buffers: [buf][operand][4]; operands: 0=Ah0 1=Ah1 2=Am0 3=Am1 4=Bh0 5=Bh1 6=Bm0 7=Bm1
    uint32_t fr[2][8][4];
    #define LOAD_FRAGS(buf, kt) do {                                   \
        uint32_t ko = (uint32_t)(kt) * 32u;                            \
        ldm4(fr[buf][0], aAddr + ko);                                  \
        ldm4(fr[buf][1], aAddr + 16u*KS*2u + ko);                      \
        ldm4(fr[buf][2], aAddr + DA + ko);                             \
        ldm4(fr[buf][3], aAddr + DA + 16u*KS*2u + ko);                 \
        ldm4(fr[buf][4], bAddr + ko);                                  \
        ldm4(fr[buf][5], bAddr + 16u*KS*2u + ko);                      \
        ldm4(fr[buf][6], bAddr + DBo + ko);                            \
        ldm4(fr[buf][7], bAddr + DBo + 16u*KS*2u + ko);                \
    } while (0)

    LOAD_FRAGS(0, 0);
    #pragma unroll
    for (int kt = 0; kt < 18; kt++) {
        const int cur = kt & 1;
        if (kt < 17) LOAD_FRAGS(cur ^ 1, kt + 1);
        // hh: Ah x Bh
        mma16816(acc[0][0], fr[cur][0], fr[cur][4][0], fr[cur][4][1]);
        mma16816(acc[0][1], fr[cur][0], fr[cur][4][2], fr[cur][4][3]);
        mma16816(acc[0][2], fr[cur][0], fr[cur][5][0], fr[cur][5][1]);
        mma16816(acc[0][3], fr[cur][0], fr[cur][5][2], fr[cur][5][3]);
        mma16816(acc[1][0], fr[cur][1], fr[cur][4][0], fr[cur][4][1]);
        mma16816(acc[1][1], fr[cur][1], fr[cur][4][2], fr[cur][4][3]);
        mma16816(acc[1][2], fr[cur][1], fr[cur][5][0], fr[cur][5][1]);
        mma16816(acc[1][3], fr[cur][1], fr[cur][5][2], fr[cur][5][3]);
        // hm: Ah x Bm
        mma16816(acc[0][0], fr[cur][0], fr[cur][6][0], fr[cur][6][1]);
        mma16816(acc[0][1], fr[cur][0], fr[cur][6][2], fr[cur][6][3]);
        mma16816(acc[0][2], fr[cur][0], fr[cur][7][0], fr[cur][7][1]);
        mma16816(acc[0][3], fr[cur][0], fr[cur][7][2], fr[cur][7][3]);
        mma16816(acc[1][0], fr[cur][1], fr[cur][6][0], fr[cur][6][1]);
        mma16816(acc[1][1], fr[cur][1], fr[cur][6][2], fr[cur][6][3]);
        mma16816(acc[1][2], fr[cur][1], fr[cur][7][0], fr[cur][7][1]);
        mma16816(acc[1][3], fr[cur][1], fr[cur][7][2], fr[cur][7][3]);
        // mh: Am x Bh
        mma16816(acc[0][0], fr[cur][2], fr[cur][4][0], fr[cur][4][1]);
        mma16816(acc[0][1], fr[cur][2], fr[cur][4][2], fr[cur][4][3]);
        mma16816(acc[0][2], fr[cur][2], fr[cur][5][0], fr[cur][5][1]);
        mma16816(acc[0][3], fr[cur][2], fr[cur][5][2], fr[cur][5][3]);
        mma16816(acc[1][0], fr[cur][3], fr[cur][4][0], fr[cur][4][1]);
        mma16816(acc[1][1], fr[cur][3], fr[cur][4][2], fr[cur][4][3]);
        mma16816(acc[1][2], fr[cur][3], fr[cur][5][0], fr[cur][5][1]);
        mma16816(acc[1][3], fr[cur][3], fr[cur][5][2], fr[cur][5][3]);
    }
    #undef LOAD_FRAGS

    // ---- phase 5: epilogue — bias+relu, pool over this warp's 32 rows ----
    float* poolS = (float*)(esm + E_POOL);
    float* nrmS  = (float*)(esm + E_NRM);
    {
        const int p2 = lane & 3;
        float cs[8];
        #pragma unroll
        for (int ni = 0; ni < 4; ni++) {
            #pragma unroll
            for (int cc = 0; cc < 2; cc++) {
                int col = ncol + ni*8 + p2*2 + cc;
                float bz = b2S[col];
                float s = 0.f;
                #pragma unroll
                for (int mi = 0; mi < 2; mi++) {
                    s += fmaxf(acc[mi][ni][cc]   + bz, 0.f);
                    s += fmaxf(acc[mi][ni][2+cc] + bz, 0.f);
                }
                cs[ni*2 + cc] = s;
            }
        }
        #pragma unroll
        for (int off = 4; off <= 16; off <<= 1)
            #pragma unroll
            for (int j = 0; j < 8; j++)
                cs[j] += __shfl_xor_sync(0xffffffffu, cs[j], off);
        if (lane < 4) {
            int im = (wid & 3) >> 1, rh = wid & 1;
            float* pp = poolS + im*128 + rh*64;
            #pragma unroll
            for (int ni = 0; ni < 4; ni++)
                #pragma unroll
                for (int cc = 0; cc < 2; cc++)
                    pp[ncol + ni*8 + lane*2 + cc] = cs[ni*2 + cc];
        }
    }
    __syncthreads();

    // ---- phase 6: linear 64->128 + l2norm ----
    {
        int im = tid >> 7, d = tid & 127;
        const float* pp = poolS + im*128;
        float s = 0.f;
        #pragma unroll 8
        for (int icx = 0; icx < 64; icx++)
            s += (pp[icx] + pp[64 + icx]) * __ldg(&lw[icx*128 + d]);
        float e = __ldg(&lb[d]) + s * (1.f/64.f);
        float sq = e*e;
        #pragma unroll
        for (int o = 16; o > 0; o >>= 1) sq += __shfl_xor_sync(0xffffffffu, sq, o);
        if (lane == 0) nrmS[wid] = sq;
        __syncthreads();
        float tot = nrmS[im*4+0] + nrmS[im*4+1] + nrmS[im*4+2] + nrmS[im*4+3];
        float inv = 1.f / fmaxf(sqrtf(tot), 1e-12f);
        g_emb[(size_t)(g*2 + im)*128 + d] = e * inv;
    }
}

// ---------------- fused: A = emb[t]@emb[t+1]^T/TAU, + row/col softmax -> Lb/Rb ----
__global__ void a_soft_kernel(float* __restrict__ outA) {
    extern __shared__ float sm[];
    float* Xs  = sm;                 // k-major emb X; later buf A [r*132+c]
    float* Ys  = sm + 128*132;
    float* mR  = sm + 2*128*132;
    float* iR  = mR + 128;
    float* mC  = iR + 128;
    float* iC  = mC + 128;
    int bt = blockIdx.x; int b = bt / 9; int t = bt % 9;
    const float* X = g_emb + (size_t)((b*TT + t)*NP)*128;
    const float* Y = g_emb + (size_t)((b*TT + t + 1)*NP)*128;
    int tid = threadIdx.x;
    for (int idx = tid; idx < 16384; idx += 256) {
        int k = idx & 127; int r = idx >> 7;
        Xs[k*132 + r] = X[r*128 + k];
        Ys[k*132 + r] = Y[r*128 + k];
    }
    __syncthreads();
    int ty = tid >> 4, tx = tid & 15;
    int r0 = ty*8, c0 = tx*8;
    float acc[8][8];
    #pragma unroll
    for (int i = 0; i < 8; i++)
        #pragma unroll
        for (int j = 0; j < 8; j++) acc[i][j] = 0.f;
    for (int k = 0; k < 128; k++) {
        float4 a0 = *(const float4*)&Xs[k*132 + r0];
        float4 a1 = *(const float4*)&Xs[k*132 + r0 + 4];
        float4 b0 = *(const float4*)&Ys[k*132 + c0];
        float4 b1 = *(const float4*)&Ys[k*132 + c0 + 4];
        float av[8] = {a0.x,a0.y,a0.z,a0.w,a1.x,a1.y,a1.z,a1.w};
        float bv[8] = {b0.x,b0.y,b0.z,b0.w,b1.x,b1.y,b1.z,b1.w};
        #pragma unroll
        for (int i = 0; i < 8; i++)
            #pragma unroll
            for (int j = 0; j < 8; j++) acc[i][j] += av[i]*bv[j];
    }
    __syncthreads();
    const float invtau = 1.f / TAUF;
    #pragma unroll
    for (int i = 0; i < 8; i++)
        #pragma unroll
        for (int j = 0; j < 8; j++)
            Xs[(r0+i)*132 + c0 + j] = acc[i][j] * invtau;
    __syncthreads();

    float* dst = outA + (size_t)bt*16384;
    for (int idx = tid; idx < 16384; idx += 256) {
        int r = idx >> 7, c = idx & 127;
        dst[idx] = Xs[r*132 + c];
    }

    if (t == 8) {
        for (int idx = tid; idx < 16384; idx += 256) {
            int r = idx >> 7, c = idx & 127;
            g_Lb[0][(size_t)(b*8 + 0)*MATSZ + idx] = (r == c) ? 1.f : 0.f;
        }
        return;
    }

    if (tid < 128) {
        int r = tid;
        float m = -1e30f;
        for (int c = 0; c < 128; c++) m = fmaxf(m, Xs[r*132 + c]);
        float s = 0.f;
        for (int c = 0; c < 128; c++) s += expf(Xs[r*132 + c] - m);
        mR[r] = m; iR[r] = 1.f / s;
    } else {
        int r = tid - 128;
        float m = -1e30f;
        for (int c = 0; c < 128; c++) m = fmaxf(m, Xs[c*132 + r]);
        float s = 0.f;
        for (int c = 0; c < 128; c++) s += expf(Xs[c*132 + r] - m);
        mC[r] = m; iC[r] = 1.f / s;
    }
    __syncthreads();

    if (tid >= 128) {
        float* dR = g_Rb[0] + (size_t)(b*8 + t)*MATSZ;
        for (int idx = tid - 128; idx < 16384; idx += 128) {
            int r = idx >> 7, c = idx & 127;
            dR[idx] = expf(Xs[c*132 + r] - mC[r]) * iC[r];
        }
    } else if (t >= 1) {
        float* dL = g_Lb[0] + (size_t)(b*8 + t)*MATSZ;
        for (int idx = tid; idx < 16384; idx += 128) {
            int r = idx >> 7, c = idx & 127;
            dL[idx] = expf(Xs[r*132 + c] - mR[r]) * iR[r];
        }
    }
}

// ---------------- scan GEMM: 64x64 block tile, 4x4 per thread ----------------
#define GS 68                            // padded smem stride (floats)
#define SCAN_SMEM ((size_t)(2*128*GS)*4) // 69632 B

__device__ __forceinline__ void gemm_tile_64(
    const float* __restrict__ A, const float* __restrict__ Bm,
    float* __restrict__ C, int trow, int tcol, float* As, float* Bs)
{
    int tid = threadIdx.x;
    for (int idx = tid; idx < 8192; idx += 256) {     // As[k][r] 128 x 64
        int r = idx >> 7; int k = idx & 127;
        As[k*GS + r] = A[(trow + r)*128 + k];
    }
    for (int idx = tid; idx < 8192; idx += 256) {     // Bs[k][c] 128 x 64
        int c = idx & 63; int k = idx >> 6;
        Bs[k*GS + c] = Bm[k*128 + tcol + c];
    }
    __syncthreads();
    int ty = tid >> 4, tx = tid & 15;
    int r0 = 4*ty, c0 = 4*tx;
    float acc[4][4];
    #pragma unroll
    for (int i = 0; i < 4; i++)
        #pragma unroll
        for (int j = 0; j < 4; j++) acc[i][j] = 0.f;
    #pragma unroll 4
    for (int k = 0; k < 128; k++) {
        float4 a = *(const float4*)&As[k*GS + r0];
        float4 b = *(const float4*)&Bs[k*GS + c0];
        float av[4] = {a.x, a.y, a.z, a.w};
        float bv[4] = {b.x, b.y, b.z, b.w};
        #pragma unroll
        for (int i = 0; i < 4; i++)
            #pragma unroll
            for (int j = 0; j < 4; j++) acc[i][j] += av[i]*bv[j];
    }
    #pragma unroll
    for (int i = 0; i < 4; i++) {
        float4 o = make_float4(acc[i][0], acc[i][1], acc[i][2], acc[i][3]);
        *(float4*)&C[(trow + r0 + i)*128 + tcol + c0] = o;
    }
}

__global__ void scan_step_kernel(int d, int pin) {
    extern __shared__ float gsm[];
    float* As = gsm; float* Bs = gsm + 128*GS;
    int b = blockIdx.z;
    int side = blockIdx.y >> 3; int j = blockIdx.y & 7;
    int tile = blockIdx.x; int trow = (tile >> 1)*64, tcol = (tile & 1)*64;
    const float* bin = side ? g_Rb[pin]   : g_Lb[pin];
    float*       bout = side ? g_Rb[1-pin] : g_Lb[1-pin];
    const float* Mj = bin + (size_t)(b*8 + j)*MATSZ;
    float*       O  = bout + (size_t)(b*8 + j)*MATSZ;
    if (j < d) {
        for (int i = threadIdx.x; i < 1024; i += 256) {
            int r = trow + (i >> 4); int c4 = tcol + (i & 15)*4;
            *(float4*)&O[r*128 + c4] = *(const float4*)&Mj[r*128 + c4];
        }
        return;
    }
    const float* Md = bin + (size_t)(b*8 + j - d)*MATSZ;
    const float* Am = side ? Md : Mj;
    const float* Bm = side ? Mj : Md;
    gemm_tile_64(Am, Bm, O, trow, tcol, As, Bs);
}

__global__ void at_kernel() {    // At_k = Q_{k-1} @ P_{k-1}
    extern __shared__ float gsm[];
    float* As = gsm; float* Bs = gsm + 128*GS;
    int b = blockIdx.z; int kk = blockIdx.y;
    int tile = blockIdx.x; int trow = (tile >> 1)*64, tcol = (tile & 1)*64;
    gemm_tile_64(g_Rb[1] + (size_t)(b*8 + kk)*MATSZ,
                 g_Lb[1] + (size_t)(b*8 + kk)*MATSZ,
                 g_At    + (size_t)(b*8 + kk)*MATSZ, trow, tcol, As, Bs);
}

// column log-softmax diag
__global__ void loss_kernel() {
    __shared__ float red[128];
    int bk = blockIdx.x;
    const float* M = g_At + (size_t)bk*MATSZ;
    int c = threadIdx.x;
    float m = -1e30f, s = 0.f, dv = 0.f;
    for (int r = 0; r < 128; r++) {
        float v = M[r*128 + c];
        if (r == c) dv = v;
        float nm = fmaxf(m, v);
        s = s*expf(m - nm) + expf(v - nm);
        m = nm;
    }
    red[c] = dv - (m + logf(s));
    __syncthreads();
    for (int o = 64; o > 0; o >>= 1) {
        if (c < o) red[c] += red[c + o];
        __syncthreads();
    }
    if (c == 0) g_partial[bk] = red[0];
}

__global__ void final_kernel(float* __restrict__ out_loss) {
    float s = 0.f;
    for (int i = 0; i < 64; i++) s += g_partial[i];
    out_loss[0] = -s / (8.f*128.f*128.f);
}

// ---------------- launch ----------------
extern "C" void kernel_launch(void* const* d_in, const int* in_sizes, int n_in,
                              void* d_out, int out_size) {
    const float* seq = (const float*)d_in[0];
    const float* c1w = (const float*)d_in[1];
    const float* c1b = (const float*)d_in[2];
    const float* c2w = (const float*)d_in[3];
    const float* c2b = (const float*)d_in[4];
    const float* lw  = (const float*)d_in[5];
    const float* lb  = (const float*)d_in[6];
    float* out = (float*)d_out;

    int a_off = out_size - (BB*NT*MATSZ);   // expected 1 (loss scalar first)
    if (a_off < 0) a_off = 0;
    float* Aout = out + a_off;

    size_t as_smem = (size_t)(2*128*132 + 512) * 4;
    cudaFuncSetAttribute(encoder_hmma_kernel, cudaFuncAttributeMaxDynamicSharedMemorySize, ENC_SMEM_BYTES);
    cudaFuncSetAttribute(a_soft_kernel, cudaFuncAttributeMaxDynamicSharedMemorySize, (int)as_smem);
    cudaFuncSetAttribute(scan_step_kernel, cudaFuncAttributeMaxDynamicSharedMemorySize, (int)SCAN_SMEM);
    cudaFuncSetAttribute(at_kernel, cudaFuncAttributeMaxDynamicSharedMemorySize, (int)SCAN_SMEM);

    encoder_hmma_kernel<<<IMGS/2, 256, ENC_SMEM_BYTES>>>(seq, c1w, c1b, c2w, c2b, lw, lb);
    a_soft_kernel<<<BB*NT, 256, as_smem>>>(Aout);
    dim3 gscan(4, 16, 8);
    scan_step_kernel<<<gscan, 256, SCAN_SMEM>>>(1, 0);
    scan_step_kernel<<<gscan, 256, SCAN_SMEM>>>(2, 1);
    scan_step_kernel<<<gscan, 256, SCAN_SMEM>>>(4, 0);
    at_kernel<<<dim3(4, 8, 8), 256, SCAN_SMEM>>>();
    loss_kernel<<<64, 128>>>();
    if (a_off >= 1) final_kernel<<<1, 1>>>(out);
}

// round 17
// speedup vs baseline: 1.0043x; 1.0043x over previous
#include <cuda_runtime.h>
#include <cuda_bf16.h>
#include <math.h>
#include <stdint.h>

#define BB 8
#define TT 10
#define NP 128
#define IMGS (BB*TT*NP)      // 10240
#define NT (TT-1)            // 9
#define MATSZ (NP*NP)        // 16384
#define TAUF 0.07f

// ---------------- device scratch (static, no allocations) ----------------
__device__ float g_emb[IMGS*128];          // normalized embeddings
__device__ float g_Lb[2][BB*8*MATSZ];      // prefix-product ping-pong
__device__ float g_Rb[2][BB*8*MATSZ];      // suffix-product ping-pong
__device__ float g_At[BB*8*MATSZ];
__device__ float g_partial[64];

// ===================== HMMA helpers (baseline PTX, sm_80+) =====================
__device__ __forceinline__ uint32_t smem_u32(const void* p) {
    uint32_t a;
    asm("{ .reg .u64 t; cvta.to.shared.u64 t, %1; cvt.u32.u64 %0, t; }" : "=r"(a) : "l"(p));
    return a;
}
__device__ __forceinline__ void ldm4(uint32_t* r, uint32_t addr) {
    asm volatile("ldmatrix.sync.aligned.m8n8.x4.shared.b16 {%0,%1,%2,%3}, [%4];"
        : "=r"(r[0]), "=r"(r[1]), "=r"(r[2]), "=r"(r[3]) : "r"(addr));
}
__device__ __forceinline__ void mma16816(float* d, const uint32_t* a, uint32_t b0, uint32_t b1) {
    asm volatile(
        "mma.sync.aligned.m16n8k16.row.col.f32.bf16.bf16.f32 "
        "{%0,%1,%2,%3}, {%4,%5,%6,%7}, {%8,%9}, {%0,%1,%2,%3};"
        : "+f"(d[0]), "+f"(d[1]), "+f"(d[2]), "+f"(d[3])
        : "r"(a[0]), "r"(a[1]), "r"(a[2]), "r"(a[3]), "r"(b0), "r"(b1));
}

// ===================== fused encoder (HMMA, split bf16, kt-outer pipelined) ==========
// CTA = 2 images, 8 warps. conv1 -> regs; v = h + m; conv2 GEMM [128,288,64]
// = hh + hm + mh. Warp tile 32x32. Per kt: load 8 frags once, issue 24 mma,
// double-buffered so ldmatrix of kt+1 overlaps mma of kt.
#define KS 296                         // padded K stride (bf16) -> 592B rows
#define E_AHI 0
#define E_ALO 75776                    // 128*296*2  (A_m)
#define E_BHI 151552
#define E_BLO 189440                   // + 64*296*2 (B_m)
#define E_B2  227328                   // 64 f32
#define E_POOL 227584
#define E_NRM  228608
#define ENC_SMEM_BYTES 228640
#define DA ((uint32_t)(E_ALO - E_AHI))
#define DBo ((uint32_t)(E_BLO - E_BHI))

extern "C" __global__ void __launch_bounds__(256, 1)
encoder_hmma_kernel(const float* __restrict__ seq,
    const float* __restrict__ c1w, const float* __restrict__ c1b,
    const float* __restrict__ c2w, const float* __restrict__ c2b,
    const float* __restrict__ lw,  const float* __restrict__ lb)
{
    extern __shared__ __align__(16) char esm[];
    const int tid = threadIdx.x;
    const int wid = tid >> 5, lane = tid & 31;
    const int g = blockIdx.x;

    // ---- phase 1: stage img + conv1 weights into (future) A region ----
    float* imgS = (float*)(esm + E_AHI);           // 2048 f32
    float* w1S  = (float*)(esm + E_AHI + 8192);    // 288 f32
    float* b1S  = w1S + 288;                       // 32 f32
    for (int i = tid; i < 2048; i += 256) imgS[i] = seq[(size_t)g*2048 + i];
    for (int i = tid; i < 288;  i += 256) w1S[i] = c1w[i];
    if (tid < 32)  b1S[tid] = c1b[tid];
    __syncthreads();

    // ---- conv1 into regs: ic = tid&31, positions pos = i*8 + (tid>>5) ----
    const int ic = tid & 31;
    const int wgrp = tid >> 5;
    float wr[9];
    #pragma unroll
    for (int j = 0; j < 9; j++) wr[j] = w1S[ic*9 + j];
    const float bias1 = b1S[ic];
    float v[64];
    #pragma unroll
    for (int i = 0; i < 64; i++) {
        int pos = i*8 + wgrp;                   // 0..511
        int im = pos >> 8, y = (pos >> 4) & 15, x = pos & 15;
        const float* ib = imgS + im*1024;
        float s = bias1;
        #pragma unroll
        for (int dy2 = 0; dy2 < 3; dy2++) {
            int iy = 2*y + dy2;
            if (iy < 32) {
                #pragma unroll
                for (int dx2 = 0; dx2 < 3; dx2++) {
                    int ix = 2*x + dx2;
                    if (ix < 32) s += ib[iy*32 + ix] * wr[dy2*3 + dx2];
                }
            }
        }
        v[i] = fmaxf(s, 0.f);
    }
    __syncthreads();

    // ---- phase 2: zero A region; build B_h/B_m; stage conv2 bias ----
    {
        uint4 z4 = make_uint4(0u, 0u, 0u, 0u);
        uint4* az = (uint4*)esm;                // bytes [0, 151552)
        for (int i = tid; i < 151552/16; i += 256) az[i] = z4;
    }
    {
        __nv_bfloat16* Bh = (__nv_bfloat16*)(esm + E_BHI);
        __nv_bfloat16* Bm = (__nv_bfloat16*)(esm + E_BLO);
        for (int i = tid; i < 64*288; i += 256) {
            int oc = i / 288; int k = i - oc*288;
            float w = __ldg(&c2w[i]);
            __nv_bfloat16 h = __float2bfloat16(w);
            float r1 = w - __bfloat162float(h);
            Bh[oc*KS + k] = h;
            Bm[oc*KS + k] = __float2bfloat16(r1);
        }
    }
    float* b2S = (float*)(esm + E_B2);
    if (tid < 64) b2S[tid] = c2b[tid];
    __syncthreads();

    // ---- phase 3: scatter conv1 regs into A_h / A_m ----
    {
        __nv_bfloat16* Ah = (__nv_bfloat16*)(esm + E_AHI);
        __nv_bfloat16* Am = (__nv_bfloat16*)(esm + E_ALO);
        #pragma unroll
        for (int i = 0; i < 64; i++) {
            int pos = i*8 + wgrp;
            int im = pos >> 8, y = (pos >> 4) & 15, x = pos & 15;
            float val = v[i];
            __nv_bfloat16 hv = __float2bfloat16(val);
            float r1 = val - __bfloat162float(hv);
            __nv_bfloat16 mv = __float2bfloat16(r1);
            #pragma unroll
            for (int dy = 0; dy < 3; dy++) {
                int ty = y - dy;
                if (ty >= 0 && (ty & 1) == 0) {
                    int oy = ty >> 1;
                    #pragma unroll
                    for (int dx = 0; dx < 3; dx++) {
                        int tx = x - dx;
                        if (tx >= 0 && (tx & 1) == 0) {
                            int ox = tx >> 1;
                            int r = im*64 + oy*8 + ox;
                            int k = ic*9 + dy*3 + dx;
                            Ah[r*KS + k] = hv;
                            Am[r*KS + k] = mv;
                        }
                    }
                }
            }
        }
    }
    __syncthreads();

    // ---- phase 4: HMMA, kt-outer, 8 frag loads + 24 mma per kt, double-buffered ----
    const uint32_t sb = smem_u32(esm);
    const int mrow = (wid & 3) * 32;
    const int ncol = (wid >> 2) * 32;
    float acc[2][4][4];
    #pragma unroll
    for (int a = 0; a < 2; a++)
        #pragma unroll
        for (int b = 0; b < 4; b++)
            #pragma unroll
            for (int c = 0; c < 4; c++) acc[a][b][c] = 0.f;

    const uint32_t aAddr = sb + E_AHI +
        (uint32_t)(((mrow + (lane & 15)) * KS + ((lane & 16) ? 8 : 0)) * 2);
    const uint32_t bAddr = sb + E_BHI +
        (uint32_t)(((ncol + (lane & 7) + ((lane & 16) ? 8 : 0)) * KS + ((lane & 8) ? 8 : 0)) * 2);

    // fragment buffers: [buf][operand][4]; operands: 0=Ah0 1=Ah1 2=Am0 3=Am1 4=Bh0 5=Bh1 6=Bm0 7=Bm1
    uint32_t fr[2][8][4];
    #define LOAD_FRAGS(buf, kt) do {                                   \
        uint32_t ko = (uint32_t)(kt) * 32u;                            \
        ldm4(fr[buf][0], aAddr + ko);                                  \
        ldm4(fr[buf][1], aAddr + 16u*KS*2u + ko);                      \
        ldm4(fr[buf][2], aAddr + DA + ko);                             \
        ldm4(fr[buf][3], aAddr + DA + 16u*KS*2u + ko);                 \
        ldm4(fr[buf][4], bAddr + ko);                                  \
        ldm4(fr[buf][5], bAddr + 16u*KS*2u + ko);                      \
        ldm4(fr[buf][6], bAddr + DBo + ko);                            \
        ldm4(fr[buf][7], bAddr + DBo + 16u*KS*2u + ko);                \
    } while (0)

    LOAD_FRAGS(0, 0);
    #pragma unroll
    for (int kt = 0; kt < 18; kt++) {
        const int cur = kt & 1;
        if (kt < 17) LOAD_FRAGS(cur ^ 1, kt + 1);
        // hh: Ah x Bh
        mma16816(acc[0][0], fr[cur][0], fr[cur][4][0], fr[cur][4][1]);
        mma16816(acc[0][1], fr[cur][0], fr[cur][4][2], fr[cur][4][3]);
        mma16816(acc[0][2], fr[cur][0], fr[cur][5][0], fr[cur][5][1]);
        mma16816(acc[0][3], fr[cur][0], fr[cur][5][2], fr[cur][5][3]);
        mma16816(acc[1][0], fr[cur][1], fr[cur][4][0], fr[cur][4][1]);
        mma16816(acc[1][1], fr[cur][1], fr[cur][4][2], fr[cur][4][3]);
        mma16816(acc[1][2], fr[cur][1], fr[cur][5][0], fr[cur][5][1]);
        mma16816(acc[1][3], fr[cur][1], fr[cur][5][2], fr[cur][5][3]);
        // hm: Ah x Bm
        mma16816(acc[0][0], fr[cur][0], fr[cur][6][0], fr[cur][6][1]);
        mma16816(acc[0][1], fr[cur][0], fr[cur][6][2], fr[cur][6][3]);
        mma16816(acc[0][2], fr[cur][0], fr[cur][7][0], fr[cur][7][1]);
        mma16816(acc[0][3], fr[cur][0], fr[cur][7][2], fr[cur][7][3]);
        mma16816(acc[1][0], fr[cur][1], fr[cur][6][0], fr[cur][6][1]);
        mma16816(acc[1][1], fr[cur][1], fr[cur][6][2], fr[cur][6][3]);
        mma16816(acc[1][2], fr[cur][1], fr[cur][7][0], fr[cur][7][1]);
        mma16816(acc[1][3], fr[cur][1], fr[cur][7][2], fr[cur][7][3]);
        // mh: Am x Bh
        mma16816(acc[0][0], fr[cur][2], fr[cur][4][0], fr[cur][4][1]);
        mma16816(acc[0][1], fr[cur][2], fr[cur][4][2], fr[cur][4][3]);
        mma16816(acc[0][2], fr[cur][2], fr[cur][5][0], fr[cur][5][1]);
        mma16816(acc[0][3], fr[cur][2], fr[cur][5][2], fr[cur][5][3]);
        mma16816(acc[1][0], fr[cur][3], fr[cur][4][0], fr[cur][4][1]);
        mma16816(acc[1][1], fr[cur][3], fr[cur][4][2], fr[cur][4][3]);
        mma16816(acc[1][2], fr[cur][3], fr[cur][5][0], fr[cur][5][1]);
        mma16816(acc[1][3], fr[cur][3], fr[cur][5][2], fr[cur][5][3]);
    }
    #undef LOAD_FRAGS

    // ---- phase 5: epilogue — bias+relu, pool over this warp's 32 rows ----
    float* poolS = (float*)(esm + E_POOL);
    float* nrmS  = (float*)(esm + E_NRM);
    {
        const int p2 = lane & 3;
        float cs[8];
        #pragma unroll
        for (int ni = 0; ni < 4; ni++) {
            #pragma unroll
            for (int cc = 0; cc < 2; cc++) {
                int col = ncol + ni*8 + p2*2 + cc;
                float bz = b2S[col];
                float s = 0.f;
                #pragma unroll
                for (int mi = 0; mi < 2; mi++) {
                    s += fmaxf(acc[mi][ni][cc]   + bz, 0.f);
                    s += fmaxf(acc[mi][ni][2+cc] + bz, 0.f);
                }
                cs[ni*2 + cc] = s;
            }
        }
        #pragma unroll
        for (int off = 4; off <= 16; off <<= 1)
            #pragma unroll
            for (int j = 0; j < 8; j++)
                cs[j] += __shfl_xor_sync(0xffffffffu, cs[j], off);
        if (lane < 4) {
            int im = (wid & 3) >> 1, rh = wid & 1;
            float* pp = poolS + im*128 + rh*64;
            #pragma unroll
            for (int ni = 0; ni < 4; ni++)
                #pragma unroll
                for (int cc = 0; cc < 2; cc++)
                    pp[ncol + ni*8 + lane*2 + cc] = cs[ni*2 + cc];
        }
    }
    __syncthreads();

    // ---- phase 6: linear 64->128 + l2norm ----
    {
        int im = tid >> 7, d = tid & 127;
        const float* pp = poolS + im*128;
        float s = 0.f;
        #pragma unroll 8
        for (int icx = 0; icx < 64; icx++)
            s += (pp[icx] + pp[64 + icx]) * __ldg(&lw[icx*128 + d]);
        float e = __ldg(&lb[d]) + s * (1.f/64.f);
        float sq = e*e;
        #pragma unroll
        for (int o = 16; o > 0; o >>= 1) sq += __shfl_xor_sync(0xffffffffu, sq, o);
        if (lane == 0) nrmS[wid] = sq;
        __syncthreads();
        float tot = nrmS[im*4+0] + nrmS[im*4+1] + nrmS[im*4+2] + nrmS[im*4+3];
        float inv = 1.f / fmaxf(sqrtf(tot), 1e-12f);
        g_emb[(size_t)(g*2 + im)*128 + d] = e * inv;
    }
}

// ---------------- fused: A = emb[t]@emb[t+1]^T/TAU, + row/col softmax -> Lb/Rb ----
__global__ void a_soft_kernel(float* __restrict__ outA) {
    extern __shared__ float sm[];
    float* Xs  = sm;                 // k-major emb X; later buf A [r*132+c]
    float* Ys  = sm + 128*132;
    float* mR  = sm + 2*128*132;
    float* iR  = mR + 128;
    float* mC  = iR + 128;
    float* iC  = mC + 128;
    int bt = blockIdx.x; int b = bt / 9; int t = bt % 9;
    const float* X = g_emb + (size_t)((b*TT + t)*NP)*128;
    const float* Y = g_emb + (size_t)((b*TT + t + 1)*NP)*128;
    int tid = threadIdx.x;
    for (int idx = tid; idx < 16384; idx += 256) {
        int k = idx & 127; int r = idx >> 7;
        Xs[k*132 + r] = X[r*128 + k];
        Ys[k*132 + r] = Y[r*128 + k];
    }
    __syncthreads();
    int ty = tid >> 4, tx = tid & 15;
    int r0 = ty*8, c0 = tx*8;
    float acc[8][8];
    #pragma unroll
    for (int i = 0; i < 8; i++)
        #pragma unroll
        for (int j = 0; j < 8; j++) acc[i][j] = 0.f;
    for (int k = 0; k < 128; k++) {
        float4 a0 = *(const float4*)&Xs[k*132 + r0];
        float4 a1 = *(const float4*)&Xs[k*132 + r0 + 4];
        float4 b0 = *(const float4*)&Ys[k*132 + c0];
        float4 b1 = *(const float4*)&Ys[k*132 + c0 + 4];
        float av[8] = {a0.x,a0.y,a0.z,a0.w,a1.x,a1.y,a1.z,a1.w};
        float bv[8] = {b0.x,b0.y,b0.z,b0.w,b1.x,b1.y,b1.z,b1.w};
        #pragma unroll
        for (int i = 0; i < 8; i++)
            #pragma unroll
            for (int j = 0; j < 8; j++) acc[i][j] += av[i]*bv[j];
    }
    __syncthreads();
    const float invtau = 1.f / TAUF;
    #pragma unroll
    for (int i = 0; i < 8; i++)
        #pragma unroll
        for (int j = 0; j < 8; j++)
            Xs[(r0+i)*132 + c0 + j] = acc[i][j] * invtau;
    __syncthreads();

    float* dst = outA + (size_t)bt*16384;
    for (int idx = tid; idx < 16384; idx += 256) {
        int r = idx >> 7, c = idx & 127;
        dst[idx] = Xs[r*132 + c];
    }

    if (t == 8) {
        for (int idx = tid; idx < 16384; idx += 256) {
            int r = idx >> 7, c = idx & 127;
            g_Lb[0][(size_t)(b*8 + 0)*MATSZ + idx] = (r == c) ? 1.f : 0.f;
        }
        return;
    }

    if (tid < 128) {
        int r = tid;
        float m = -1e30f;
        for (int c = 0; c < 128; c++) m = fmaxf(m, Xs[r*132 + c]);
        float s = 0.f;
        for (int c = 0; c < 128; c++) s += expf(Xs[r*132 + c] - m);
        mR[r] = m; iR[r] = 1.f / s;
    } else {
        int r = tid - 128;
        float m = -1e30f;
        for (int c = 0; c < 128; c++) m = fmaxf(m, Xs[c*132 + r]);
        float s = 0.f;
        for (int c = 0; c < 128; c++) s += expf(Xs[c*132 + r] - m);
        mC[r] = m; iC[r] = 1.f / s;
    }
    __syncthreads();

    if (tid >= 128) {
        float* dR = g_Rb[0] + (size_t)(b*8 + t)*MATSZ;
        for (int idx = tid - 128; idx < 16384; idx += 128) {
            int r = idx >> 7, c = idx & 127;
            dR[idx] = expf(Xs[c*132 + r] - mC[r]) * iC[r];
        }
    } else if (t >= 1) {
        float* dL = g_Lb[0] + (size_t)(b*8 + t)*MATSZ;
        for (int idx = tid; idx < 16384; idx += 128) {
            int r = idx >> 7, c = idx & 127;
            dL[idx] = expf(Xs[r*132 + c] - mR[r]) * iR[r];
        }
    }
}

// ---------------- scan GEMM: 64x64 block tile, 4x4 per thread ----------------
#define GS 68                            // padded smem stride (floats)
#define SCAN_SMEM ((size_t)(2*128*GS)*4) // 69632 B

__device__ __forceinline__ void gemm_tile_64(
    const float* __restrict__ A, const float* __restrict__ Bm,
    float* __restrict__ C, int trow, int tcol, float* As, float* Bs)
{
    int tid = threadIdx.x;
    for (int idx = tid; idx < 8192; idx += 256) {     // As[k][r] 128 x 64
        int r = idx >> 7; int k = idx & 127;
        As[k*GS + r] = A[(trow + r)*128 + k];
    }
    for (int idx = tid; idx < 8192; idx += 256) {     // Bs[k][c] 128 x 64
        int c = idx & 63; int k = idx >> 6;
        Bs[k*GS + c] = Bm[k*128 + tcol + c];
    }
    __syncthreads();
    int ty = tid >> 4, tx = tid & 15;
    int r0 = 4*ty, c0 = 4*tx;
    float acc[4][4];
    #pragma unroll
    for (int i = 0; i < 4; i++)
        #pragma unroll
        for (int j = 0; j < 4; j++) acc[i][j] = 0.f;
    #pragma unroll 4
    for (int k = 0; k < 128; k++) {
        float4 a = *(const float4*)&As[k*GS + r0];
        float4 b = *(const float4*)&Bs[k*GS + c0];
        float av[4] = {a.x, a.y, a.z, a.w};
        float bv[4] = {b.x, b.y, b.z, b.w};
        #pragma unroll
        for (int i = 0; i < 4; i++)
            #pragma unroll
            for (int j = 0; j < 4; j++) acc[i][j] += av[i]*bv[j];
    }
    #pragma unroll
    for (int i = 0; i < 4; i++) {
        float4 o = make_float4(acc[i][0], acc[i][1], acc[i][2], acc[i][3]);
        *(float4*)&C[(trow + r0 + i)*128 + tcol + c0] = o;
    }
}

__global__ void scan_step_kernel(int d, int pin) {
    extern __shared__ float gsm[];
    float* As = gsm; float* Bs = gsm + 128*GS;
    int b = blockIdx.z;
    int side = blockIdx.y >> 3; int j = blockIdx.y & 7;
    int tile = blockIdx.x; int trow = (tile >> 1)*64, tcol = (tile & 1)*64;
    const float* bin = side ? g_Rb[pin]   : g_Lb[pin];
    float*       bout = side ? g_Rb[1-pin] : g_Lb[1-pin];
    const float* Mj = bin + (size_t)(b*8 + j)*MATSZ;
    float*       O  = bout + (size_t)(b*8 + j)*MATSZ;
    if (j < d) {
        for (int i = threadIdx.x; i < 1024; i += 256) {
            int r = trow + (i >> 4); int c4 = tcol + (i & 15)*4;
            *(float4*)&O[r*128 + c4] = *(const float4*)&Mj[r*128 + c4];
        }
        return;
    }
    const float* Md = bin + (size_t)(b*8 + j - d)*MATSZ;
    const float* Am = side ? Md : Mj;
    const float* Bm = side ? Mj : Md;
    gemm_tile_64(Am, Bm, O, trow, tcol, As, Bs);
}

__global__ void at_kernel() {    // At_k = Q_{k-1} @ P_{k-1}
    extern __shared__ float gsm[];
    float* As = gsm; float* Bs = gsm + 128*GS;
    int b = blockIdx.z; int kk = blockIdx.y;
    int tile = blockIdx.x; int trow = (tile >> 1)*64, tcol = (tile & 1)*64;
    gemm_tile_64(g_Rb[1] + (size_t)(b*8 + kk)*MATSZ,
                 g_Lb[1] + (size_t)(b*8 + kk)*MATSZ,
                 g_At    + (size_t)(b*8 + kk)*MATSZ, trow, tcol, As, Bs);
}

// column log-softmax diag
__global__ void loss_kernel() {
    __shared__ float red[128];
    int bk = blockIdx.x;
    const float* M = g_At + (size_t)bk*MATSZ;
    int c = threadIdx.x;
    float m = -1e30f, s = 0.f, dv = 0.f;
    for (int r = 0; r < 128; r++) {
        float v = M[r*128 + c];
        if (r == c) dv = v;
        float nm = fmaxf(m, v);
        s = s*expf(m - nm) + expf(v - nm);
        m = nm;
    }
    red[c] = dv - (m + logf(s));
    __syncthreads();
    for (int o = 64; o > 0; o >>= 1) {
        if (c < o) red[c] += red[c + o];
        __syncthreads();
    }
    if (c == 0) g_partial[bk] = red[0];
}

__global__ void final_kernel(float* __restrict__ out_loss) {
    float s = 0.f;
    for (int i = 0; i < 64; i++) s += g_partial[i];
    out_loss[0] = -s / (8.f*128.f*128.f);
}

// ---------------- launch ----------------
extern "C" void kernel_launch(void* const* d_in, const int* in_sizes, int n_in,
                              void* d_out, int out_size) {
    const float* seq = (const float*)d_in[0];
    const float* c1w = (const float*)d_in[1];
    const float* c1b = (const float*)d_in[2];
    const float* c2w = (const float*)d_in[3];
    const float* c2b = (const float*)d_in[4];
    const float* lw  = (const float*)d_in[5];
    const float* lb  = (const float*)d_in[6];
    float* out = (float*)d_out;

    int a_off = out_size - (BB*NT*MATSZ);   // expected 1 (loss scalar first)
    if (a_off < 0) a_off = 0;
    float* Aout = out + a_off;

    size_t as_smem = (size_t)(2*128*132 + 512) * 4;
    cudaFuncSetAttribute(encoder_hmma_kernel, cudaFuncAttributeMaxDynamicSharedMemorySize, ENC_SMEM_BYTES);
    cudaFuncSetAttribute(a_soft_kernel, cudaFuncAttributeMaxDynamicSharedMemorySize, (int)as_smem);
    cudaFuncSetAttribute(scan_step_kernel, cudaFuncAttributeMaxDynamicSharedMemorySize, (int)SCAN_SMEM);
    cudaFuncSetAttribute(at_kernel, cudaFuncAttributeMaxDynamicSharedMemorySize, (int)SCAN_SMEM);

    encoder_hmma_kernel<<<IMGS/2, 256, ENC_SMEM_BYTES>>>(seq, c1w, c1b, c2w, c2b, lw, lb);
    a_soft_kernel<<<BB*NT, 256, as_smem>>>(Aout);
    dim3 gscan(4, 16, 8);
    scan_step_kernel<<<gscan, 256, SCAN_SMEM>>>(1, 0);
    scan_step_kernel<<<gscan, 256, SCAN_SMEM>>>(2, 1);
    scan_step_kernel<<<gscan, 256, SCAN_SMEM>>>(4, 0);
    at_kernel<<<dim3(4, 8, 8), 256, SCAN_SMEM>>>();
    loss_kernel<<<64, 128>>>();
    if (a_off >= 1) final_kernel<<<1, 1>>>(out);
}